// round 14
// baseline (speedup 1.0000x reference)
#include <cuda_runtime.h>
#include <cuda_fp16.h>
#include <cstdint>

#define B_  16
#define C_  64
#define O_  64
#define H_  64
#define Wd_ 64
#define HW_ (H_ * Wd_)
#define EPSF 1e-6f
#define SLOPE 0.01f

// ---- scratch ----
__device__ float g_cmax0[B_ * HW_];
__device__ float g_cmin0[B_ * HW_];
__device__ float g_cmax1[B_ * HW_];
__device__ float g_cmin1[B_ * HW_];
// per-lane A-fragment image: [par][tap][k2][mt][lane][4 u32] = 18432 u32 (fp16x2)
__device__ __align__(16) uint32_t g_wfrag[18432];
// NHWC-permuted fp16 x: [b][h][w][cperm] — 128 B per pixel
__device__ __align__(16) unsigned char g_xh[B_ * HW_ * 128];

// ------------------------------------------------------------------
// Kernel 1: min/max by parity + NHWC fp16 pack, no staging smem.
// Block = 128 pixels. Thread: g = tid>>5 = chunk id (par,k2,kh),
// pxg = tid&31 -> pixels pxg*4..pxg*4+3. 8 LDG.128 in, 4 STG.128 out.
// ------------------------------------------------------------------
__global__ void __launch_bounds__(256)
chan_pack_kernel(const float* __restrict__ x) {
    __shared__ float4 s_mx[8][32], s_mn[8][32];

    const int tid = threadIdx.x;
    const int g   = tid >> 5;               // chunk id = par*4 + k2*2 + kh
    const int pxg = tid & 31;
    const int par = g >> 2, k2 = (g >> 1) & 1, kh = g & 1;
    const int b   = blockIdx.y;
    const int px0 = blockIdx.x * 128;

    const float* xb = x + (size_t)b * C_ * HW_ + px0 + pxg * 4;

    float4 v[8];
    float4 mx = make_float4(-1e30f, -1e30f, -1e30f, -1e30f);
    float4 mn = make_float4( 1e30f,  1e30f,  1e30f,  1e30f);
#pragma unroll
    for (int chlo = 0; chlo < 8; chlo++) {
        int cg = 2 * (k2 * 16 + kh * 8 + chlo) + par;
        float4 vv = *reinterpret_cast<const float4*>(xb + (size_t)cg * HW_);
        v[chlo] = vv;
        mx.x = fmaxf(mx.x, vv.x); mn.x = fminf(mn.x, vv.x);
        mx.y = fmaxf(mx.y, vv.y); mn.y = fminf(mn.y, vv.y);
        mx.z = fmaxf(mx.z, vv.z); mn.z = fminf(mn.z, vv.z);
        mx.w = fmaxf(mx.w, vv.w); mn.w = fminf(mn.w, vv.w);
    }
    s_mx[g][pxg] = mx; s_mn[g][pxg] = mn;

    // direct pack: per pixel e, one 16B chunk (8 fp16, chlo 0..7)
    unsigned char* dstb = g_xh + (size_t)(b * HW_ + px0 + pxg * 4) * 128 + g * 16;
#pragma unroll
    for (int e = 0; e < 4; e++) {
        uint32_t q[4];
#pragma unroll
        for (int p = 0; p < 4; p++) {
            const float* f0 = &v[2 * p].x;
            const float* f1 = &v[2 * p + 1].x;
            __half2 h2 = __floats2half2_rn(f0[e], f1[e]);
            q[p] = *reinterpret_cast<uint32_t*>(&h2);
        }
        *reinterpret_cast<uint4*>(dstb + e * 128) = make_uint4(q[0], q[1], q[2], q[3]);
    }
    __syncthreads();

    // minmax combine across the 4 chunk-groups of each parity
    if (tid < 64) {
        int pr = tid >> 5, pg = tid & 31;
        float4 a = s_mx[pr * 4 + 0][pg], c = s_mx[pr * 4 + 1][pg];
        float4 d = s_mx[pr * 4 + 2][pg], f = s_mx[pr * 4 + 3][pg];
        float4 rmx = make_float4(fmaxf(fmaxf(a.x,c.x), fmaxf(d.x,f.x)),
                                 fmaxf(fmaxf(a.y,c.y), fmaxf(d.y,f.y)),
                                 fmaxf(fmaxf(a.z,c.z), fmaxf(d.z,f.z)),
                                 fmaxf(fmaxf(a.w,c.w), fmaxf(d.w,f.w)));
        a = s_mn[pr * 4 + 0][pg]; c = s_mn[pr * 4 + 1][pg];
        d = s_mn[pr * 4 + 2][pg]; f = s_mn[pr * 4 + 3][pg];
        float4 rmn = make_float4(fminf(fminf(a.x,c.x), fminf(d.x,f.x)),
                                 fminf(fminf(a.y,c.y), fminf(d.y,f.y)),
                                 fminf(fminf(a.z,c.z), fminf(d.z,f.z)),
                                 fminf(fminf(a.w,c.w), fminf(d.w,f.w)));
        int gi4 = (b * HW_ + px0) / 4 + pg;
        if (pr == 0) {
            reinterpret_cast<float4*>(g_cmax0)[gi4] = rmx;
            reinterpret_cast<float4*>(g_cmin0)[gi4] = rmn;
        } else {
            reinterpret_cast<float4*>(g_cmax1)[gi4] = rmx;
            reinterpret_cast<float4*>(g_cmin1)[gi4] = rmn;
        }
    }
}

// ------------------------------------------------------------------
// Kernel 2: weight prep -> per-lane fp16 mma A fragments (m16n8k16 layout).
// ------------------------------------------------------------------
__global__ void wprep_kernel(const float* __restrict__ Wt) {
    int e = blockIdx.x * blockDim.x + threadIdx.x;
    if (e >= 18432) return;
    int q    = e & 3;
    int lane = (e >> 2) & 31;
    int mt   = (e >> 7) & 3;
    int rest = e >> 9;
    int k2   = rest & 1;  rest >>= 1;
    int tap  = rest % 9;  rest /= 9;
    int par  = rest & 1;

    int r = lane >> 2, c = (lane & 3) * 2;
    int o  = mt * 16 + r + ((q & 1) ? 8 : 0);
    int ch = c + ((q & 2) ? 8 : 0);
    int i = tap / 3, j = tap % 3;

    uint32_t packed = 0;
#pragma unroll
    for (int hp = 0; hp < 2; hp++) {
        int cg = 2 * (k2 * 16 + ch + hp) + par;
        float v = Wt[(size_t)o * 576 + cg * 9 + j * 3 + i];
        packed |= (uint32_t)__half_as_ushort(__float2half(v)) << (hp * 16);
    }
    g_wfrag[e] = packed;
}

// ------------------------------------------------------------------
// PTX helpers
// ------------------------------------------------------------------
__device__ __forceinline__ uint32_t smem_to_u32(const void* p) {
    uint32_t a;
    asm("{ .reg .u64 t; cvta.to.shared.u64 t, %1; cvt.u32.u64 %0, t; }"
        : "=r"(a) : "l"(p));
    return a;
}
__device__ __forceinline__ void ldsm4(uint32_t* r, uint32_t addr) {
    asm volatile("ldmatrix.sync.aligned.m8n8.x4.shared.b16 {%0,%1,%2,%3}, [%4];"
                 : "=r"(r[0]), "=r"(r[1]), "=r"(r[2]), "=r"(r[3]) : "r"(addr));
}
__device__ __forceinline__ void mma16816(float* d, const uint4 a,
                                         uint32_t b0, uint32_t b1) {
    asm volatile("mma.sync.aligned.m16n8k16.row.col.f32.f16.f16.f32 "
                 "{%0,%1,%2,%3}, {%4,%5,%6,%7}, {%8,%9}, {%0,%1,%2,%3};"
                 : "+f"(d[0]), "+f"(d[1]), "+f"(d[2]), "+f"(d[3])
                 : "r"(a.x), "r"(a.y), "r"(a.z), "r"(a.w), "r"(b0), "r"(b1));
}
__device__ __forceinline__ void cpasync16(uint32_t dst, const void* src) {
    asm volatile("cp.async.ca.shared.global [%0], [%1], 16;"
                 :: "r"(dst), "l"(src) : "memory");
}

// smem: X buffers (2 x 23040), s0[2][128], s1[2][128]
#define XBUF   23040
#define SOFF0  46080
#define SOFF1  47104
#define SMEM_TOTAL 48128

// ------------------------------------------------------------------
// Main kernel: CTA = batch b, 8 rows x 32 cols as TWO 8x16 tiles,
// double-buffered cp.async. Warp-tile M32xN32: warp wid ->
// rows rA=2*(wid&3), rA+1; o-groups mtbase=(wid>>2)*2, +1.
// ------------------------------------------------------------------
__global__ void __launch_bounds__(256, 2)
conv_mma_kernel(const float* __restrict__ bias,
                float* __restrict__ out) {
    extern __shared__ __align__(16) unsigned char smem[];
    const uint32_t sb32 = smem_to_u32(smem);
    float* s0s = reinterpret_cast<float*>(smem + SOFF0);
    float* s1s = reinterpret_cast<float*>(smem + SOFF1);

    const int tid = threadIdx.x;
    const int wid = tid >> 5;
    const int lid = tid & 31;
    const int b  = blockIdx.z;
    const int h0 = blockIdx.y * 8;
    const int wb = blockIdx.x * 32;

    const unsigned char* xbase_g = g_xh + ((size_t)b << 12) * 128;

    // ---- fill tile 0 (async) ----
#pragma unroll 1
    for (int idx = tid; idx < 1440; idx += 256) {
        int chunk = idx & 7;
        int pos   = idx >> 3;
        int r  = pos / 18;
        int cl = pos - r * 18;
        int hin = min(max(h0 + r  - 1, 0), 63);
        int win = min(max(wb + cl - 1, 0), 63);
        cpasync16(sb32 + r * 2304 + cl * 128 + ((chunk ^ (cl & 7)) << 4),
                  xbase_g + ((size_t)(hin * 64 + win)) * 128 + chunk * 16);
    }
    asm volatile("cp.async.commit_group;" ::: "memory");

    // ---- compute s0/s1 for BOTH tiles (overlaps fills) ----
    {
        int tile = tid >> 7;
        int lt   = tid & 127;
        int srow = lt >> 4, wloc = lt & 15;
        int h = h0 + srow, w = wb + tile * 16 + wloc;
        int base = b * HW_;
        float mx0 = -1e30f, mn0 = 1e30f, mx1 = -1e30f, mn1 = 1e30f;
#pragma unroll
        for (int di = -1; di <= 1; di++)
#pragma unroll
            for (int dj = -1; dj <= 1; dj++) {
                int hh = min(max(h + di, 0), 63);
                int ww = min(max(w + dj, 0), 63);
                int idx = base + hh * 64 + ww;
                mx0 = fmaxf(mx0, g_cmax0[idx]); mn0 = fminf(mn0, g_cmin0[idx]);
                mx1 = fmaxf(mx1, g_cmax1[idx]); mn1 = fminf(mn1, g_cmin1[idx]);
            }
        s0s[tid] = (mx0 - mn0) + EPSF;
        s1s[tid] = (mx1 - mn1) + EPSF;
    }

    // ---- fill tile 1 (async, second group) ----
#pragma unroll 1
    for (int idx = tid; idx < 1440; idx += 256) {
        int chunk = idx & 7;
        int pos   = idx >> 3;
        int r  = pos / 18;
        int cl = pos - r * 18;
        int hin = min(max(h0 + r  - 1, 0), 63);
        int win = min(max(wb + 16 + cl - 1, 0), 63);
        cpasync16(sb32 + XBUF + r * 2304 + cl * 128 + ((chunk ^ (cl & 7)) << 4),
                  xbase_g + ((size_t)(hin * 64 + win)) * 128 + chunk * 16);
    }
    asm volatile("cp.async.commit_group;" ::: "memory");
    asm volatile("cp.async.wait_group 1;" ::: "memory");   // tile-0 ready
    __syncthreads();

    // ---- hoisted per-lane constants ----
    const int lm = lid & 15, kh = lid >> 4;
    const int rA = (wid & 3) * 2;
    const int mtbase = (wid >> 2) * 2;

    uint32_t rowbA[3], colj[3], swzj[3];
#pragma unroll
    for (int i = 0; i < 3; i++) rowbA[i] = (uint32_t)((rA + i) * 2304);
#pragma unroll
    for (int j = 0; j < 3; j++) {
        int cB = lm + j;
        colj[j] = (uint32_t)(cB * 128);
        swzj[j] = (uint32_t)((cB & 7) << 4);
    }
    const uint32_t kh16 = (uint32_t)(kh * 16);
    const uint4* __restrict__ wf = reinterpret_cast<const uint4*>(g_wfrag);
    const int g = lid >> 2, t4 = lid & 3;

#pragma unroll 1
    for (int tile = 0; tile < 2; tile++) {
        const uint32_t xb32 = sb32 + tile * XBUF;
        const int w0 = wb + tile * 16;

        float accE[32], accO[32];
#pragma unroll
        for (int i = 0; i < 32; i++) { accE[i] = 0.f; accO[i] = 0.f; }

        // acc layout: [mtl(2)][row(2)][nt(2)][4]
        auto gemm_par = [&](float (&acc)[32], int par) {
            const uint4* wsp = wf + (size_t)(par * 9) * 256 + mtbase * 32 + lid;
            const uint32_t parq = (uint32_t)(par * 64) + kh16;
#pragma unroll
            for (int tap = 0; tap < 9; tap++) {
                const int i = tap / 3, j = tap % 3;
                const uint32_t xrowA = xb32 + rowbA[i] + colj[j];
                const uint32_t bin0 = parq ^ swzj[j];
                const uint4* wtap = wsp + tap * 256;
#pragma unroll
                for (int k2 = 0; k2 < 2; k2++) {
                    uint32_t bA[4], bB[4];
                    uint32_t boff = bin0 ^ (uint32_t)(k2 << 5);
                    ldsm4(bA, xrowA + boff);
                    ldsm4(bB, xrowA + 2304 + boff);
                    const uint4* wk = wtap + k2 * 128;
                    uint4 a0 = wk[0];
                    uint4 a1 = wk[32];
                    mma16816(acc + 0,  a0, bA[0], bA[2]);
                    mma16816(acc + 4,  a0, bA[1], bA[3]);
                    mma16816(acc + 8,  a0, bB[0], bB[2]);
                    mma16816(acc + 12, a0, bB[1], bB[3]);
                    mma16816(acc + 16, a1, bA[0], bA[2]);
                    mma16816(acc + 20, a1, bA[1], bA[3]);
                    mma16816(acc + 24, a1, bB[0], bB[2]);
                    mma16816(acc + 28, a1, bB[1], bB[3]);
                }
            }
        };

        gemm_par(accE, 0);
        gemm_par(accO, 1);

        // ---- epilogue ----
#pragma unroll
        for (int rr = 0; rr < 2; rr++) {
            const int srow = rA + rr;
            const int hrow = h0 + srow;
            float i0[2][2], i1[2][2], sc0[2][2], sc1[2][2];
#pragma unroll
            for (int nt = 0; nt < 2; nt++) {
                int wloc = nt * 8 + 2 * t4;
#pragma unroll
                for (int e = 0; e < 2; e++) {
                    float a0v = s0s[tile * 128 + srow * 16 + wloc + e];
                    float a1v = s1s[tile * 128 + srow * 16 + wloc + e];
                    sc0[nt][e] = a0v; sc1[nt][e] = a1v;
                    i0[nt][e] = 1.0f / a0v; i1[nt][e] = 1.0f / a1v;
                }
            }
#pragma unroll
            for (int mtl = 0; mtl < 2; mtl++) {
#pragma unroll
                for (int half = 0; half < 2; half++) {
                    int o = (mtbase + mtl) * 16 + g + half * 8;
                    float bo = bias[o];
                    bool odd = (o & 1) != 0;
#pragma unroll
                    for (int nt = 0; nt < 2; nt++) {
                        float2 vv;
                        float* pv = &vv.x;
#pragma unroll
                        for (int e = 0; e < 2; e++) {
                            int k = mtl * 16 + rr * 8 + nt * 4 + half * 2 + e;
                            float v = accE[k] * i0[nt][e] + accO[k] * i1[nt][e] + bo;
                            v = (v >= 0.f) ? v : (SLOPE * v);
                            v *= odd ? sc1[nt][e] : sc0[nt][e];
                            pv[e] = v;
                        }
                        int wloc = nt * 8 + 2 * t4;
                        *reinterpret_cast<float2*>(
                            out + ((size_t)(b * O_ + o) * HW_) + hrow * 64 + w0 + wloc) = vv;
                    }
                }
            }
        }

        if (tile == 0) {
            asm volatile("cp.async.wait_group 0;" ::: "memory");   // tile-1 ready
            __syncthreads();
        }
    }
}

// ------------------------------------------------------------------
extern "C" void kernel_launch(void* const* d_in, const int* in_sizes, int n_in,
                              void* d_out, int out_size) {
    const float* x    = (const float*)d_in[0];
    const float* Wt   = (const float*)d_in[1];
    const float* bias = (const float*)d_in[2];
    float* out = (float*)d_out;

    cudaFuncSetAttribute(conv_mma_kernel,
                         cudaFuncAttributeMaxDynamicSharedMemorySize, SMEM_TOTAL);

    dim3 pgrid(HW_ / 128, B_);                // (32, 16)
    chan_pack_kernel<<<pgrid, 256>>>(x);
    wprep_kernel<<<72, 256>>>(Wt);

    dim3 grid(2, 8, 16);   // w-tile pairs, h tiles, batch
    conv_mma_kernel<<<grid, 256, SMEM_TOTAL>>>(bias, out);
}